// round 1
// baseline (speedup 1.0000x reference)
#include <cuda_runtime.h>

#define NA 50000      // agents (dst)
#define NS 50000      // src nodes per graph
#define NE 600000     // edges per graph

// ---------------- device scratch (no allocations allowed) ----------------
__device__ __align__(256) float g_fs [2][NS * 128];   // src projections
__device__ __align__(256) float g_res[2][NA * 128];   // residual projections
__device__ __align__(256) float g_h  [2][NA * 128];   // per-graph GAT outputs
__device__ __align__(256) float g_el [2][NS * 4];
__device__ __align__(256) float g_er [2][NA * 4];
__device__ __align__(256) float g_wel[2][256];        // folded W_src @ attn_l : [64,4]
__device__ __align__(256) float g_wer[2][256];        // folded W_dst @ attn_r : [64,4]
__device__ int g_deg[2][NA];
__device__ int g_off[2][NA + 1];
__device__ int g_cur[2][NA];
__device__ int g_csr[2][NE];

__device__ __forceinline__ float lrelu(float x) { return x > 0.f ? x : 0.2f * x; }

__device__ __forceinline__ float wmax(float v) {
#pragma unroll
    for (int s = 16; s; s >>= 1) v = fmaxf(v, __shfl_xor_sync(0xffffffffu, v, s));
    return v;
}
__device__ __forceinline__ float wsum(float v) {
#pragma unroll
    for (int s = 16; s; s >>= 1) v += __shfl_xor_sync(0xffffffffu, v, s);
    return v;
}

// ---------------- tiny kernels ----------------
__global__ void zero_deg_kernel() {
    int i = blockIdx.x * blockDim.x + threadIdx.x;
    if (i < 2 * NA) (&g_deg[0][0])[i] = 0;
}

// w_out[i][h] = sum_d W[i][h*32+d] * attn[h][d]   (W:[64,128], attn:[4,32])
__global__ void fold_attn(const float* __restrict__ W, const float* __restrict__ attn,
                          int g, int lr) {
    int t = threadIdx.x;          // 256 threads
    int i = t >> 2, h = t & 3;
    float a = 0.f;
#pragma unroll
    for (int d = 0; d < 32; d++) a = fmaf(W[i * 128 + h * 32 + d], attn[h * 32 + d], a);
    float* o = lr ? g_wer[g] : g_wel[g];
    o[i * 4 + h] = a;
}

// out[N,4] = X[N,64] @ w[64,4]
__global__ __launch_bounds__(256) void proj_h4(const float* __restrict__ X,
                                               int g, int lr, int N) {
    __shared__ float Xs[64][64];
    __shared__ float ws[256];
    const float* w = lr ? g_wer[g] : g_wel[g];
    float* out = lr ? g_er[g] : g_el[g];
    int t = threadIdx.x;
    int row0 = blockIdx.x * 64;
    ws[t] = w[t];
#pragma unroll
    for (int i = 0; i < 4; i++) {
        int idx = t + i * 256;
        int r = idx >> 4, kc = (idx & 15) << 2;
        float4 v = make_float4(0.f, 0.f, 0.f, 0.f);
        if (row0 + r < N) v = *(const float4*)(X + (size_t)(row0 + r) * 64 + kc);
        *(float4*)&Xs[r][kc] = v;
    }
    __syncthreads();
    int r = t >> 2, h = t & 3;
    float a = 0.f;
#pragma unroll 16
    for (int k = 0; k < 64; k++) a = fmaf(Xs[r][k], ws[k * 4 + h], a);
    if (row0 + r < N) out[(size_t)(row0 + r) * 4 + h] = a;
}

// ---------------- C[N,128] = X[N,64] @ W[64,128] ----------------
// which: 0,1 -> g_fs[0/1]; 2,3 -> g_res[0/1]
__global__ __launch_bounds__(256) void gemm_n64(const float* __restrict__ X,
                                                const float* __restrict__ W,
                                                int which, int N) {
    __shared__ float Xs[64][64];
    __shared__ float Ws[64][128];
    float* C = (which < 2) ? g_fs[which] : g_res[which - 2];
    int t = threadIdx.x;
    int row0 = blockIdx.x * 64;
#pragma unroll
    for (int i = 0; i < 8; i++) {
        int idx = t + i * 256;
        ((float4*)Ws)[idx] = ((const float4*)W)[idx];
    }
#pragma unroll
    for (int i = 0; i < 4; i++) {
        int idx = t + i * 256;
        int r = idx >> 4, kc = (idx & 15) << 2;
        float4 v = make_float4(0.f, 0.f, 0.f, 0.f);
        if (row0 + r < N) v = *(const float4*)(X + (size_t)(row0 + r) * 64 + kc);
        *(float4*)&Xs[r][kc] = v;
    }
    __syncthreads();
    int tx = t & 15, ty = t >> 4;
    float acc[4][8];
#pragma unroll
    for (int i = 0; i < 4; i++)
#pragma unroll
        for (int j = 0; j < 8; j++) acc[i][j] = 0.f;

#pragma unroll 8
    for (int k = 0; k < 64; k++) {
        float xv[4];
#pragma unroll
        for (int i = 0; i < 4; i++) xv[i] = Xs[ty * 4 + i][k];
        float4 wa = *(const float4*)&Ws[k][tx * 8];
        float4 wb = *(const float4*)&Ws[k][tx * 8 + 4];
        float wv[8] = {wa.x, wa.y, wa.z, wa.w, wb.x, wb.y, wb.z, wb.w};
#pragma unroll
        for (int i = 0; i < 4; i++)
#pragma unroll
            for (int j = 0; j < 8; j++) acc[i][j] = fmaf(xv[i], wv[j], acc[i][j]);
    }
#pragma unroll
    for (int i = 0; i < 4; i++) {
        int r = row0 + ty * 4 + i;
        if (r < N) {
            float4 o1 = make_float4(acc[i][0], acc[i][1], acc[i][2], acc[i][3]);
            float4 o2 = make_float4(acc[i][4], acc[i][5], acc[i][6], acc[i][7]);
            *(float4*)(C + (size_t)r * 128 + tx * 8) = o1;
            *(float4*)(C + (size_t)r * 128 + tx * 8 + 4) = o2;
        }
    }
}

// ---------------- out = relu([h0|h1] @ Wf + bf), Wf:[256,128] ----------------
__global__ __launch_bounds__(256) void gemm_final(const float* __restrict__ Wf,
                                                  const float* __restrict__ bf,
                                                  float* __restrict__ out) {
    __shared__ float Xs[64][64];
    __shared__ float Ws[64][128];
    int t = threadIdx.x;
    int row0 = blockIdx.x * 64;
    int tx = t & 15, ty = t >> 4;
    float acc[4][8];
#pragma unroll
    for (int i = 0; i < 4; i++)
#pragma unroll
        for (int j = 0; j < 8; j++) acc[i][j] = 0.f;

    for (int kc = 0; kc < 4; kc++) {
        const float* X = (kc < 2) ? g_h[0] : g_h[1];
        int koff = (kc & 1) * 64;
        const float* Wc = Wf + kc * 64 * 128;
        __syncthreads();
#pragma unroll
        for (int i = 0; i < 8; i++) {
            int idx = t + i * 256;
            ((float4*)Ws)[idx] = ((const float4*)Wc)[idx];
        }
#pragma unroll
        for (int i = 0; i < 4; i++) {
            int idx = t + i * 256;
            int r = idx >> 4, kcol = (idx & 15) << 2;
            float4 v = make_float4(0.f, 0.f, 0.f, 0.f);
            if (row0 + r < NA)
                v = *(const float4*)(X + (size_t)(row0 + r) * 128 + koff + kcol);
            *(float4*)&Xs[r][kcol] = v;
        }
        __syncthreads();
#pragma unroll 8
        for (int k = 0; k < 64; k++) {
            float xv[4];
#pragma unroll
            for (int i = 0; i < 4; i++) xv[i] = Xs[ty * 4 + i][k];
            float4 wa = *(const float4*)&Ws[k][tx * 8];
            float4 wb = *(const float4*)&Ws[k][tx * 8 + 4];
            float wv[8] = {wa.x, wa.y, wa.z, wa.w, wb.x, wb.y, wb.z, wb.w};
#pragma unroll
            for (int i = 0; i < 4; i++)
#pragma unroll
                for (int j = 0; j < 8; j++) acc[i][j] = fmaf(xv[i], wv[j], acc[i][j]);
        }
    }
#pragma unroll
    for (int i = 0; i < 4; i++) {
        int r = row0 + ty * 4 + i;
        if (r < NA) {
            float o[8];
#pragma unroll
            for (int j = 0; j < 8; j++) o[j] = fmaxf(acc[i][j] + bf[tx * 8 + j], 0.f);
            *(float4*)(out + (size_t)r * 128 + tx * 8)     = make_float4(o[0], o[1], o[2], o[3]);
            *(float4*)(out + (size_t)r * 128 + tx * 8 + 4) = make_float4(o[4], o[5], o[6], o[7]);
        }
    }
}

// ---------------- CSR build ----------------
__global__ void count_deg(const int* __restrict__ dst, int g) {
    int i = blockIdx.x * blockDim.x + threadIdx.x;
    if (i < NE) atomicAdd(&g_deg[g][dst[i]], 1);
}

__global__ __launch_bounds__(1024) void scan2() {
    int g = blockIdx.x;
    __shared__ int sh[1024];
    __shared__ int carry;
    int t = threadIdx.x;
    if (t == 0) carry = 0;
    __syncthreads();
    for (int base = 0; base < NA; base += 1024) {
        int i = base + t;
        int v = (i < NA) ? g_deg[g][i] : 0;
        sh[t] = v;
        __syncthreads();
        for (int s = 1; s < 1024; s <<= 1) {
            int tv = (t >= s) ? sh[t - s] : 0;
            __syncthreads();
            sh[t] += tv;
            __syncthreads();
        }
        if (i < NA) {
            int e = carry + sh[t] - v;
            g_off[g][i] = e;
            g_cur[g][i] = e;
        }
        __syncthreads();
        if (t == 0) carry += sh[1023];
        __syncthreads();
    }
    if (t == 0) g_off[g][NA] = carry;
}

__global__ void scatter_e(const int* __restrict__ src, const int* __restrict__ dst, int g) {
    int i = blockIdx.x * blockDim.x + threadIdx.x;
    if (i < NE) {
        int d = dst[i];
        int p = atomicAdd(&g_cur[g][d], 1);
        g_csr[g][p] = src[i];
    }
}

// ---------------- dst-centric GAT gather: one warp per agent node ----------------
__global__ __launch_bounds__(256) void gat_gather(const float* __restrict__ b, int g) {
    int w = (blockIdx.x * 256 + threadIdx.x) >> 5;
    int lane = threadIdx.x & 31;
    if (w >= NA) return;
    const int*   __restrict__ csr = g_csr[g];
    const float* __restrict__ el  = g_el[g];
    const float* __restrict__ fs  = g_fs[g];
    int s0  = g_off[g][w];
    int deg = g_off[g][w + 1] - s0;
    float4 acc = make_float4(0.f, 0.f, 0.f, 0.f);
    int h = lane >> 3;   // features 4*lane..4*lane+3 are all head h = lane/8
    if (deg > 0) {
        float4 erv = *(const float4*)(g_er[g] + (size_t)w * 4);
        float m0 = -1e30f, m1 = -1e30f, m2 = -1e30f, m3 = -1e30f;
        for (int k = lane; k < deg; k += 32) {
            int s = csr[s0 + k];
            float4 e4 = *(const float4*)(el + (size_t)s * 4);
            m0 = fmaxf(m0, lrelu(e4.x + erv.x));
            m1 = fmaxf(m1, lrelu(e4.y + erv.y));
            m2 = fmaxf(m2, lrelu(e4.z + erv.z));
            m3 = fmaxf(m3, lrelu(e4.w + erv.w));
        }
        m0 = wmax(m0); m1 = wmax(m1); m2 = wmax(m2); m3 = wmax(m3);
        float d0 = 0.f, d1 = 0.f, d2 = 0.f, d3 = 0.f;
        for (int k = lane; k < deg; k += 32) {
            int s = csr[s0 + k];
            float4 e4 = *(const float4*)(el + (size_t)s * 4);
            d0 += __expf(lrelu(e4.x + erv.x) - m0);
            d1 += __expf(lrelu(e4.y + erv.y) - m1);
            d2 += __expf(lrelu(e4.z + erv.z) - m2);
            d3 += __expf(lrelu(e4.w + erv.w) - m3);
        }
        d0 = wsum(d0); d1 = wsum(d1); d2 = wsum(d2); d3 = wsum(d3);
        float mh  = (h == 0) ? m0 : (h == 1) ? m1 : (h == 2) ? m2 : m3;
        float dh  = (h == 0) ? d0 : (h == 1) ? d1 : (h == 2) ? d2 : d3;
        float erh = (h == 0) ? erv.x : (h == 1) ? erv.y : (h == 2) ? erv.z : erv.w;
        float inv = 1.0f / dh;
        for (int k = 0; k < deg; k++) {
            int s = csr[s0 + k];                       // uniform across warp
            float e = lrelu(el[(size_t)s * 4 + h] + erh);
            float a = __expf(e - mh) * inv;
            float4 f = *(const float4*)(fs + (size_t)s * 128 + lane * 4);
            acc.x = fmaf(f.x, a, acc.x);
            acc.y = fmaf(f.y, a, acc.y);
            acc.z = fmaf(f.z, a, acc.z);
            acc.w = fmaf(f.w, a, acc.w);
        }
    }
    float4 r4 = *(const float4*)(g_res[g] + (size_t)w * 128 + lane * 4);
    float4 b4 = *(const float4*)(b + lane * 4);
    float4 o;
    o.x = fmaxf(acc.x + r4.x + b4.x, 0.f);
    o.y = fmaxf(acc.y + r4.y + b4.y, 0.f);
    o.z = fmaxf(acc.z + r4.z + b4.z, 0.f);
    o.w = fmaxf(acc.w + r4.w + b4.w, 0.f);
    *(float4*)(g_h[g] + (size_t)w * 128 + lane * 4) = o;
}

// ---------------- launch ----------------
extern "C" void kernel_launch(void* const* d_in, const int* in_sizes, int n_in,
                              void* d_out, int out_size) {
    const float* x_gt     = (const float*)d_in[0];
    const float* x_uav    = (const float*)d_in[1];
    const float* x_agent  = (const float*)d_in[2];
    const int*   src_gt   = (const int*)d_in[3];
    const int*   dst_gt   = (const int*)d_in[4];
    const int*   src_uav  = (const int*)d_in[5];
    const int*   dst_uav  = (const int*)d_in[6];
    const float* W_src_gt = (const float*)d_in[7];
    const float* W_dst_gt = (const float*)d_in[8];
    const float* al_gt    = (const float*)d_in[9];
    const float* ar_gt    = (const float*)d_in[10];
    const float* W_res_gt = (const float*)d_in[11];
    const float* b_gt     = (const float*)d_in[12];
    const float* W_src_uav = (const float*)d_in[13];
    const float* W_dst_uav = (const float*)d_in[14];
    const float* al_uav    = (const float*)d_in[15];
    const float* ar_uav    = (const float*)d_in[16];
    const float* W_res_uav = (const float*)d_in[17];
    const float* b_uav     = (const float*)d_in[18];
    const float* W_f       = (const float*)d_in[19];
    const float* b_f       = (const float*)d_in[20];
    float* out = (float*)d_out;

    const int gR = (NA + 63) / 64;        // 782 row-tiles
    const int gE = (NE + 255) / 256;      // 2344

    zero_deg_kernel<<<(2 * NA + 255) / 256, 256>>>();

    fold_attn<<<1, 256>>>(W_src_gt,  al_gt,  0, 0);
    fold_attn<<<1, 256>>>(W_dst_gt,  ar_gt,  0, 1);
    fold_attn<<<1, 256>>>(W_src_uav, al_uav, 1, 0);
    fold_attn<<<1, 256>>>(W_dst_uav, ar_uav, 1, 1);

    proj_h4<<<gR, 256>>>(x_gt,    0, 0, NS);
    proj_h4<<<gR, 256>>>(x_agent, 0, 1, NA);
    proj_h4<<<gR, 256>>>(x_uav,   1, 0, NS);
    proj_h4<<<gR, 256>>>(x_agent, 1, 1, NA);

    gemm_n64<<<gR, 256>>>(x_gt,    W_src_gt,  0, NS);
    gemm_n64<<<gR, 256>>>(x_uav,   W_src_uav, 1, NS);
    gemm_n64<<<gR, 256>>>(x_agent, W_res_gt,  2, NA);
    gemm_n64<<<gR, 256>>>(x_agent, W_res_uav, 3, NA);

    count_deg<<<gE, 256>>>(dst_gt,  0);
    count_deg<<<gE, 256>>>(dst_uav, 1);
    scan2<<<2, 1024>>>();
    scatter_e<<<gE, 256>>>(src_gt,  dst_gt,  0);
    scatter_e<<<gE, 256>>>(src_uav, dst_uav, 1);

    gat_gather<<<(NA * 32 + 255) / 256, 256>>>(b_gt,  0);
    gat_gather<<<(NA * 32 + 255) / 256, 256>>>(b_uav, 1);

    gemm_final<<<gR, 256>>>(W_f, b_f, out);
}

// round 2
// speedup vs baseline: 1.4383x; 1.4383x over previous
#include <cuda_runtime.h>

#define NA 50000
#define NS 50000
#define NE 600000

typedef unsigned long long ull;

// ---------------- device scratch ----------------
__device__ __align__(256) float g_fs [2][NS * 128];
__device__ __align__(256) float g_res[2][NA * 128];
__device__ __align__(256) float g_h  [2][NA * 128];
__device__ __align__(256) float g_el [2][NS * 4];
__device__ __align__(256) float g_er [2][NA * 4];
__device__ __align__(256) float g_wel[2][256];
__device__ __align__(256) float g_wer[2][256];
__device__ int g_deg[2][NA];
__device__ int g_off[2][NA + 1];
__device__ int g_cur[2][NA];
__device__ int g_csr[2][NE];
__device__ int g_part[98];
__device__ int g_pb[98];

// ---------------- f32x2 helpers ----------------
__device__ __forceinline__ ull pack2(float x, float y) {
    ull r; asm("mov.b64 %0,{%1,%2};" : "=l"(r) : "f"(x), "f"(y)); return r;
}
__device__ __forceinline__ void ffma2(ull& d, ull a, ull b) {
    asm("fma.rn.f32x2 %0,%1,%2,%0;" : "+l"(d) : "l"(a), "l"(b));
}
__device__ __forceinline__ float2 unpack2(ull v) {
    float2 f; asm("mov.b64 {%0,%1},%2;" : "=f"(f.x), "=f"(f.y) : "l"(v)); return f;
}

__device__ __forceinline__ float lrelu(float x) { return x > 0.f ? x : 0.2f * x; }
__device__ __forceinline__ float wmax(float v) {
#pragma unroll
    for (int s = 16; s; s >>= 1) v = fmaxf(v, __shfl_xor_sync(0xffffffffu, v, s));
    return v;
}
__device__ __forceinline__ float wsum(float v) {
#pragma unroll
    for (int s = 16; s; s >>= 1) v += __shfl_xor_sync(0xffffffffu, v, s);
    return v;
}

// ---------------- small kernels ----------------
__global__ void zero_deg_kernel() {
    int i = blockIdx.x * blockDim.x + threadIdx.x;
    if (i < 2 * NA) (&g_deg[0][0])[i] = 0;
}

// 4 blocks: fold W[64,128] with attn[4,32] -> [64,4]
__global__ void fold4(const float* __restrict__ Wsg, const float* __restrict__ alg,
                      const float* __restrict__ Wdg, const float* __restrict__ arg_,
                      const float* __restrict__ Wsu, const float* __restrict__ alu,
                      const float* __restrict__ Wdu, const float* __restrict__ aru) {
    int b = blockIdx.x;
    const float* W = (b == 0) ? Wsg : (b == 1) ? Wdg : (b == 2) ? Wsu : Wdu;
    const float* A = (b == 0) ? alg : (b == 1) ? arg_ : (b == 2) ? alu : aru;
    float* o = (b == 0) ? g_wel[0] : (b == 1) ? g_wer[0] : (b == 2) ? g_wel[1] : g_wer[1];
    int t = threadIdx.x;
    int i = t >> 2, h = t & 3;
    float a = 0.f;
#pragma unroll
    for (int d = 0; d < 32; d++) a = fmaf(W[i * 128 + h * 32 + d], A[h * 32 + d], a);
    o[i * 4 + h] = a;
}

// ---------------- fused GEMM: C[N,128]=X[N,64]@W + e[N,4]=X@wfold ----------------
#define XSTRIDE 130
#define NBLK 391      // ceil(50000/128)
#define SMB (64 * XSTRIDE * 8 + 64 * 128 * 4)

__device__ __forceinline__ void gemm_core(
    const float* __restrict__ X, int ldx, int koff, const float* __restrict__ W,
    int row0, int N, int t, ull* XsD, float* Ws, ull acc[8][4]) {
    // fill Ws [64][128]
#pragma unroll
    for (int i = 0; i < 8; i++)
        ((float4*)Ws)[t + i * 256] = ((const float4*)W)[t + i * 256];
    // fill XsD transposed+duplicated: XsD[k][r] = (x,x)
#pragma unroll
    for (int i = 0; i < 8; i++) {
        int idx = t + i * 256;           // 2048 float4 = 128 rows x 16
        int r = idx >> 4, kc = (idx & 15) << 2;
        float4 v = make_float4(0.f, 0.f, 0.f, 0.f);
        if (row0 + r < N) v = *(const float4*)(X + (size_t)(row0 + r) * ldx + koff + kc);
        XsD[(kc + 0) * XSTRIDE + r] = pack2(v.x, v.x);
        XsD[(kc + 1) * XSTRIDE + r] = pack2(v.y, v.y);
        XsD[(kc + 2) * XSTRIDE + r] = pack2(v.z, v.z);
        XsD[(kc + 3) * XSTRIDE + r] = pack2(v.w, v.w);
    }
    __syncthreads();
    int tx = t & 15, ty = t >> 4;
    const ull* WsU = (const ull*)Ws;
#pragma unroll 4
    for (int k = 0; k < 64; k++) {
        ulonglong2 xa = *(const ulonglong2*)&XsD[k * XSTRIDE + ty * 8];
        ulonglong2 xb = *(const ulonglong2*)&XsD[k * XSTRIDE + ty * 8 + 2];
        ulonglong2 xc = *(const ulonglong2*)&XsD[k * XSTRIDE + ty * 8 + 4];
        ulonglong2 xd = *(const ulonglong2*)&XsD[k * XSTRIDE + ty * 8 + 6];
        ull xp[8] = {xa.x, xa.y, xb.x, xb.y, xc.x, xc.y, xd.x, xd.y};
        ulonglong2 w0 = *(const ulonglong2*)&WsU[k * 64 + tx * 4];
        ulonglong2 w1 = *(const ulonglong2*)&WsU[k * 64 + tx * 4 + 2];
        ull wp[4] = {w0.x, w0.y, w1.x, w1.y};
#pragma unroll
        for (int i = 0; i < 8; i++)
#pragma unroll
            for (int j = 0; j < 4; j++) ffma2(acc[i][j], xp[i], wp[j]);
    }
}

__global__ __launch_bounds__(256, 2) void gemm4(
    const float* __restrict__ x_gt, const float* __restrict__ x_uav,
    const float* __restrict__ x_agent,
    const float* __restrict__ Wsg, const float* __restrict__ Wsu,
    const float* __restrict__ Wrg, const float* __restrict__ Wru) {
    extern __shared__ char dynsm[];
    ull* XsD = (ull*)dynsm;
    float* Ws = (float*)(dynsm + 64 * XSTRIDE * 8);
    int q = blockIdx.x / NBLK;
    int blk = blockIdx.x % NBLK;
    int row0 = blk * 128;
    int t = threadIdx.x;
    const float* X = (q == 0) ? x_gt : (q == 1) ? x_uav : x_agent;
    const float* W = (q == 0) ? Wsg : (q == 1) ? Wsu : (q == 2) ? Wrg : Wru;
    float* C = (q == 0) ? g_fs[0] : (q == 1) ? g_fs[1] : (q == 2) ? g_res[0] : g_res[1];
    float* eo = (q == 0) ? g_el[0] : (q == 1) ? g_el[1] : (q == 2) ? g_er[0] : g_er[1];
    const float* wf = (q == 0) ? g_wel[0] : (q == 1) ? g_wel[1] : (q == 2) ? g_wer[0] : g_wer[1];
    const int N = 50000;

    ull acc[8][4];
#pragma unroll
    for (int i = 0; i < 8; i++)
#pragma unroll
        for (int j = 0; j < 4; j++) acc[i][j] = 0ull;

    gemm_core(X, 64, 0, W, row0, N, t, XsD, Ws, acc);

    int tx = t & 15, ty = t >> 4;
#pragma unroll
    for (int i = 0; i < 8; i++) {
        int r = row0 + ty * 8 + i;
        if (r < N) {
            float2 u0 = unpack2(acc[i][0]), u1 = unpack2(acc[i][1]);
            float2 u2 = unpack2(acc[i][2]), u3 = unpack2(acc[i][3]);
            *(float4*)(C + (size_t)r * 128 + tx * 8)     = make_float4(u0.x, u0.y, u1.x, u1.y);
            *(float4*)(C + (size_t)r * 128 + tx * 8 + 4) = make_float4(u2.x, u2.y, u3.x, u3.y);
        }
    }
    // fused attention projection: e[r][h] = sum_k x[r][k]*wf[k][h]
    {
        int r = t >> 1, hp = (t & 1) * 2;
        float a0 = 0.f, a1 = 0.f;
#pragma unroll 8
        for (int k = 0; k < 64; k++) {
            float xv = *(const float*)&XsD[k * XSTRIDE + r];
            a0 = fmaf(xv, wf[k * 4 + hp], a0);
            a1 = fmaf(xv, wf[k * 4 + hp + 1], a1);
        }
        if (row0 + r < N) {
            eo[(size_t)(row0 + r) * 4 + hp]     = a0;
            eo[(size_t)(row0 + r) * 4 + hp + 1] = a1;
        }
    }
}

// ---------------- final GEMM: out = relu([h0|h1] @ Wf + bf) ----------------
__global__ __launch_bounds__(256, 2) void gemm_final(
    const float* __restrict__ Wf, const float* __restrict__ bf,
    float* __restrict__ out) {
    extern __shared__ char dynsm[];
    ull* XsD = (ull*)dynsm;
    float* Ws = (float*)(dynsm + 64 * XSTRIDE * 8);
    int t = threadIdx.x;
    int row0 = blockIdx.x * 128;

    ull acc[8][4];
#pragma unroll
    for (int i = 0; i < 8; i++)
#pragma unroll
        for (int j = 0; j < 4; j++) acc[i][j] = 0ull;

    for (int kc = 0; kc < 4; kc++) {
        const float* X = (kc < 2) ? g_h[0] : g_h[1];
        int koff = (kc & 1) * 64;
        if (kc) __syncthreads();
        gemm_core(X, 128, koff, Wf + kc * 64 * 128, row0, NA, t, XsD, Ws, acc);
    }
    int tx = t & 15, ty = t >> 4;
#pragma unroll
    for (int i = 0; i < 8; i++) {
        int r = row0 + ty * 8 + i;
        if (r < NA) {
            float2 u0 = unpack2(acc[i][0]), u1 = unpack2(acc[i][1]);
            float2 u2 = unpack2(acc[i][2]), u3 = unpack2(acc[i][3]);
            float o[8] = {u0.x, u0.y, u1.x, u1.y, u2.x, u2.y, u3.x, u3.y};
#pragma unroll
            for (int j = 0; j < 8; j++) o[j] = fmaxf(o[j] + bf[tx * 8 + j], 0.f);
            *(float4*)(out + (size_t)r * 128 + tx * 8)     = make_float4(o[0], o[1], o[2], o[3]);
            *(float4*)(out + (size_t)r * 128 + tx * 8 + 4) = make_float4(o[4], o[5], o[6], o[7]);
        }
    }
}

// ---------------- CSR build ----------------
__global__ void count_deg(const int* __restrict__ dst_gt, const int* __restrict__ dst_uav) {
    int i = blockIdx.x * blockDim.x + threadIdx.x;
    if (i < 2 * NE) {
        int g = i >= NE;
        int idx = i - g * NE;
        const int* d = g ? dst_uav : dst_gt;
        atomicAdd(&g_deg[g][d[idx]], 1);
    }
}

__global__ __launch_bounds__(1024) void scan_partial() {
    int b = blockIdx.x, g = b / 49, cb = b % 49;
    int t = threadIdx.x, lane = t & 31, wid = t >> 5;
    int i = cb * 1024 + t;
    int v = (i < NA) ? g_deg[g][i] : 0;
#pragma unroll
    for (int s = 16; s; s >>= 1) v += __shfl_xor_sync(0xffffffffu, v, s);
    __shared__ int sh[32];
    if (lane == 0) sh[wid] = v;
    __syncthreads();
    if (wid == 0) {
        int x = sh[lane];
#pragma unroll
        for (int s = 16; s; s >>= 1) x += __shfl_xor_sync(0xffffffffu, x, s);
        if (lane == 0) g_part[b] = x;
    }
}

__global__ void scan_tops() {
    int t = threadIdx.x;
    if (t < 2) {
        int run = 0;
        for (int j = 0; j < 49; j++) {
            g_pb[t * 49 + j] = run;
            run += g_part[t * 49 + j];
        }
        g_off[t][NA] = run;
    }
}

__global__ __launch_bounds__(1024) void scan_final() {
    int b = blockIdx.x, g = b / 49, cb = b % 49;
    int t = threadIdx.x, lane = t & 31, wid = t >> 5;
    int i = cb * 1024 + t;
    int v = (i < NA) ? g_deg[g][i] : 0;
    int x = v;
#pragma unroll
    for (int s = 1; s < 32; s <<= 1) {
        int n = __shfl_up_sync(0xffffffffu, x, s);
        if (lane >= s) x += n;
    }
    __shared__ int sh[32];
    if (lane == 31) sh[wid] = x;
    __syncthreads();
    if (wid == 0) {
        int y = sh[lane];
#pragma unroll
        for (int s = 1; s < 32; s <<= 1) {
            int n = __shfl_up_sync(0xffffffffu, y, s);
            if (lane >= s) y += n;
        }
        sh[lane] = y;
    }
    __syncthreads();
    int excl = x - v + (wid ? sh[wid - 1] : 0) + g_pb[b];
    if (i < NA) {
        g_off[g][i] = excl;
        g_cur[g][i] = excl;
    }
}

__global__ void scatter_e(const int* __restrict__ src_gt, const int* __restrict__ dst_gt,
                          const int* __restrict__ src_uav, const int* __restrict__ dst_uav) {
    int i = blockIdx.x * blockDim.x + threadIdx.x;
    if (i < 2 * NE) {
        int g = i >= NE;
        int idx = i - g * NE;
        const int* d = g ? dst_uav : dst_gt;
        const int* s = g ? src_uav : src_gt;
        int dd = d[idx];
        int p = atomicAdd(&g_cur[g][dd], 1);
        g_csr[g][p] = s[idx];
    }
}

// ---------------- dst-centric GAT gather: one warp per (graph, agent) ----------------
__global__ __launch_bounds__(256) void gat_gather(const float* __restrict__ b_gt,
                                                  const float* __restrict__ b_uav) {
    int w = (blockIdx.x * 256 + threadIdx.x) >> 5;
    int lane = threadIdx.x & 31;
    if (w >= 2 * NA) return;
    int g = w >= NA;
    w -= g * NA;
    const float* bb = g ? b_uav : b_gt;
    const int*   __restrict__ csr = g_csr[g];
    const float* __restrict__ el  = g_el[g];
    const float* __restrict__ fs  = g_fs[g];
    int s0  = g_off[g][w];
    int deg = g_off[g][w + 1] - s0;
    float4 acc = make_float4(0.f, 0.f, 0.f, 0.f);
    int h = lane >> 3;
    if (deg > 0) {
        float4 erv = *(const float4*)(g_er[g] + (size_t)w * 4);
        float m0 = -1e30f, m1 = -1e30f, m2 = -1e30f, m3 = -1e30f;
        for (int k = lane; k < deg; k += 32) {
            int s = csr[s0 + k];
            float4 e4 = *(const float4*)(el + (size_t)s * 4);
            m0 = fmaxf(m0, lrelu(e4.x + erv.x));
            m1 = fmaxf(m1, lrelu(e4.y + erv.y));
            m2 = fmaxf(m2, lrelu(e4.z + erv.z));
            m3 = fmaxf(m3, lrelu(e4.w + erv.w));
        }
        m0 = wmax(m0); m1 = wmax(m1); m2 = wmax(m2); m3 = wmax(m3);
        float d0 = 0.f, d1 = 0.f, d2 = 0.f, d3 = 0.f;
        for (int k = lane; k < deg; k += 32) {
            int s = csr[s0 + k];
            float4 e4 = *(const float4*)(el + (size_t)s * 4);
            d0 += __expf(lrelu(e4.x + erv.x) - m0);
            d1 += __expf(lrelu(e4.y + erv.y) - m1);
            d2 += __expf(lrelu(e4.z + erv.z) - m2);
            d3 += __expf(lrelu(e4.w + erv.w) - m3);
        }
        d0 = wsum(d0); d1 = wsum(d1); d2 = wsum(d2); d3 = wsum(d3);
        float mh  = (h == 0) ? m0 : (h == 1) ? m1 : (h == 2) ? m2 : m3;
        float dh  = (h == 0) ? d0 : (h == 1) ? d1 : (h == 2) ? d2 : d3;
        float erh = (h == 0) ? erv.x : (h == 1) ? erv.y : (h == 2) ? erv.z : erv.w;
        float inv = 1.0f / dh;
        for (int k = 0; k < deg; k++) {
            int s = csr[s0 + k];
            float e = lrelu(el[(size_t)s * 4 + h] + erh);
            float a = __expf(e - mh) * inv;
            float4 f = *(const float4*)(fs + (size_t)s * 128 + lane * 4);
            acc.x = fmaf(f.x, a, acc.x);
            acc.y = fmaf(f.y, a, acc.y);
            acc.z = fmaf(f.z, a, acc.z);
            acc.w = fmaf(f.w, a, acc.w);
        }
    }
    float4 r4 = *(const float4*)(g_res[g] + (size_t)w * 128 + lane * 4);
    float4 b4 = *(const float4*)(bb + lane * 4);
    float4 o;
    o.x = fmaxf(acc.x + r4.x + b4.x, 0.f);
    o.y = fmaxf(acc.y + r4.y + b4.y, 0.f);
    o.z = fmaxf(acc.z + r4.z + b4.z, 0.f);
    o.w = fmaxf(acc.w + r4.w + b4.w, 0.f);
    *(float4*)(g_h[g] + (size_t)w * 128 + lane * 4) = o;
}

// ---------------- launch ----------------
extern "C" void kernel_launch(void* const* d_in, const int* in_sizes, int n_in,
                              void* d_out, int out_size) {
    const float* x_gt     = (const float*)d_in[0];
    const float* x_uav    = (const float*)d_in[1];
    const float* x_agent  = (const float*)d_in[2];
    const int*   src_gt   = (const int*)d_in[3];
    const int*   dst_gt   = (const int*)d_in[4];
    const int*   src_uav  = (const int*)d_in[5];
    const int*   dst_uav  = (const int*)d_in[6];
    const float* W_src_gt = (const float*)d_in[7];
    const float* W_dst_gt = (const float*)d_in[8];
    const float* al_gt    = (const float*)d_in[9];
    const float* ar_gt    = (const float*)d_in[10];
    const float* W_res_gt = (const float*)d_in[11];
    const float* b_gt     = (const float*)d_in[12];
    const float* W_src_uav = (const float*)d_in[13];
    const float* W_dst_uav = (const float*)d_in[14];
    const float* al_uav    = (const float*)d_in[15];
    const float* ar_uav    = (const float*)d_in[16];
    const float* W_res_uav = (const float*)d_in[17];
    const float* b_uav     = (const float*)d_in[18];
    const float* W_f       = (const float*)d_in[19];
    const float* b_f       = (const float*)d_in[20];
    float* out = (float*)d_out;

    static int smem_set = 0;
    if (!smem_set) {
        cudaFuncSetAttribute(gemm4, cudaFuncAttributeMaxDynamicSharedMemorySize, SMB);
        cudaFuncSetAttribute(gemm_final, cudaFuncAttributeMaxDynamicSharedMemorySize, SMB);
        smem_set = 1;
    }

    const int gE2 = (2 * NE + 255) / 256;

    zero_deg_kernel<<<(2 * NA + 255) / 256, 256>>>();
    fold4<<<4, 256>>>(W_src_gt, al_gt, W_dst_gt, ar_gt, W_src_uav, al_uav, W_dst_uav, ar_uav);

    gemm4<<<4 * NBLK, 256, SMB>>>(x_gt, x_uav, x_agent, W_src_gt, W_src_uav, W_res_gt, W_res_uav);

    count_deg<<<gE2, 256>>>(dst_gt, dst_uav);
    scan_partial<<<98, 1024>>>();
    scan_tops<<<1, 32>>>();
    scan_final<<<98, 1024>>>();
    scatter_e<<<gE2, 256>>>(src_gt, dst_gt, src_uav, dst_uav);

    gat_gather<<<(2 * NA * 32 + 255) / 256, 256>>>(b_gt, b_uav);

    gemm_final<<<NBLK, 256, SMB>>>(W_f, b_f, out);
}